// round 12
// baseline (speedup 1.0000x reference)
#include <cuda_runtime.h>
#include <cuda_fp16.h>
#include <cstdint>

// Problem constants
#define BB   8
#define LL   512
#define DD   1024
#define SS   6144
#define NSPAN (BB * SS)    // 49152 spans
#define MM   (BB * LL)     // 4096 GEMM rows
#define LP1  (LL + 1)      // 513 prefix rows
#define NT   8             // prefix tiles along t
#define TW   (LL / NT)     // 64 timesteps per tile

// Scratch (device globals: no allocation allowed)
__device__ float g_p[MM * DD];          // p = h @ W^T          (16 MB)
__device__ float g_g[BB * LP1 * DD];    // prefix sums of p     (16.8 MB)
__device__ float g_part[BB * NT * DD];  // per-tile partial sums (256 KB)
__device__ int   g_is32;                // span_idx dtype flag

// ---------------------------------------------------------------------------
// helpers
// ---------------------------------------------------------------------------
__device__ __forceinline__ void mma_f16(float c[4], const uint32_t a[4], const uint32_t b[2]) {
    asm volatile(
        "mma.sync.aligned.m16n8k16.row.col.f32.f16.f16.f32 "
        "{%0,%1,%2,%3}, {%4,%5,%6,%7}, {%8,%9}, {%0,%1,%2,%3};"
        : "+f"(c[0]), "+f"(c[1]), "+f"(c[2]), "+f"(c[3])
        : "r"(a[0]), "r"(a[1]), "r"(a[2]), "r"(a[3]),
          "r"(b[0]), "r"(b[1]));
}

__device__ __forceinline__ uint32_t pack_half2(float x, float y) {
    __half2 h = __float22half2_rn(make_float2(x, y));
    return *reinterpret_cast<uint32_t*>(&h);
}

// ---------------------------------------------------------------------------
// Kernel 1: GEMM (R10 known-good, ~35us). p[m][n] = sum_d h[m][d] * W[n][d]
// 128x256x32 block tile, 256 threads (8 warps as 2x4), 64x64 warp tiles,
// fp16 m16n8k16 MMA with fp32 accumulate. KPH=40 conflict-free.
// ---------------------------------------------------------------------------
#define BM 128
#define BN 256
#define BK 32
#define KPH 40          // padded row stride in halves

__global__ void __launch_bounds__(256, 1)
gemm_f16_kernel(const float* __restrict__ A,   // h  [4096,1024]
                const float* __restrict__ Wm,  // W  [1024,1024]
                float* __restrict__ P)         // p  [4096,1024]
{
    __shared__ __half As[BM * KPH];   // 10 KB
    __shared__ __half Bs[BN * KPH];   // 20 KB

    const int tid  = threadIdx.x;
    const int warp = tid >> 5;
    const int lane = tid & 31;
    const int wm   = warp >> 2;   // 0..1  (64-row slab)
    const int wn   = warp & 3;    // 0..3  (64-col slab)
    const int m0   = blockIdx.x * BM;
    const int n0   = blockIdx.y * BN;

    const int lr = tid >> 3;
    const int lc = (tid & 7) * 4;

    const float* Ag = A  + (size_t)(m0 + lr) * DD + lc;
    const float* Bg = Wm + (size_t)(n0 + lr) * DD + lc;

    float acc[4][8][4];
    #pragma unroll
    for (int mt = 0; mt < 4; mt++)
        #pragma unroll
        for (int nt = 0; nt < 8; nt++)
            #pragma unroll
            for (int r = 0; r < 4; r++) acc[mt][nt][r] = 0.0f;

    float4 ra[4], rb[8];
    #pragma unroll
    for (int j = 0; j < 4; j++)
        ra[j] = *(const float4*)(Ag + (size_t)j * 32 * DD);
    #pragma unroll
    for (int j = 0; j < 8; j++)
        rb[j] = *(const float4*)(Bg + (size_t)j * 32 * DD);

    const int NKT = DD / BK;  // 32
    for (int kt = 0; kt < NKT; kt++) {
        #pragma unroll
        for (int j = 0; j < 4; j++) {
            float4 a = ra[j];
            uint2 pa;
            pa.x = pack_half2(a.x, a.y); pa.y = pack_half2(a.z, a.w);
            *(uint2*)(&As[(lr + j * 32) * KPH + lc]) = pa;
        }
        #pragma unroll
        for (int j = 0; j < 8; j++) {
            float4 b = rb[j];
            uint2 pb;
            pb.x = pack_half2(b.x, b.y); pb.y = pack_half2(b.z, b.w);
            *(uint2*)(&Bs[(lr + j * 32) * KPH + lc]) = pb;
        }
        __syncthreads();

        if (kt + 1 < NKT) {
            const int ko = (kt + 1) * BK;
            #pragma unroll
            for (int j = 0; j < 4; j++)
                ra[j] = *(const float4*)(Ag + (size_t)j * 32 * DD + ko);
            #pragma unroll
            for (int j = 0; j < 8; j++)
                rb[j] = *(const float4*)(Bg + (size_t)j * 32 * DD + ko);
        }

        #pragma unroll
        for (int ks = 0; ks < 2; ks++) {
            const int kb = ks * 16 + (lane & 3) * 2;
            const int rA = wm * 64 + (lane >> 2);

            uint32_t af[4][4];
            #pragma unroll
            for (int mt = 0; mt < 4; mt++) {
                const int r = rA + mt * 16;
                af[mt][0] = *(const uint32_t*)(&As[r       * KPH + kb]);
                af[mt][1] = *(const uint32_t*)(&As[(r + 8) * KPH + kb]);
                af[mt][2] = *(const uint32_t*)(&As[r       * KPH + kb + 8]);
                af[mt][3] = *(const uint32_t*)(&As[(r + 8) * KPH + kb + 8]);
            }
            uint32_t bf[8][2];
            #pragma unroll
            for (int nt = 0; nt < 8; nt++) {
                const int n = wn * 64 + nt * 8 + (lane >> 2);
                bf[nt][0] = *(const uint32_t*)(&Bs[n * KPH + kb]);
                bf[nt][1] = *(const uint32_t*)(&Bs[n * KPH + kb + 8]);
            }
            #pragma unroll
            for (int mt = 0; mt < 4; mt++)
                #pragma unroll
                for (int nt = 0; nt < 8; nt++)
                    mma_f16(acc[mt][nt], af[mt], bf[nt]);
        }
        __syncthreads();
    }

    const int mrow = m0 + wm * 64 + (lane >> 2);
    const int ncol = n0 + wn * 64 + (lane & 3) * 2;
    #pragma unroll
    for (int mt = 0; mt < 4; mt++) {
        #pragma unroll
        for (int nt = 0; nt < 8; nt++) {
            const int r = mrow + mt * 16;
            const int c = ncol + nt * 8;
            *(float2*)(&P[(size_t)r       * DD + c]) = make_float2(acc[mt][nt][0], acc[mt][nt][1]);
            *(float2*)(&P[(size_t)(r + 8) * DD + c]) = make_float2(acc[mt][nt][2], acc[mt][nt][3]);
        }
    }
}

// ---------------------------------------------------------------------------
// Kernel W: invalid-span writer (runs on a forked stream, overlapped with
// the GEMM which leaves DRAM ~96% idle). One block per span; valid spans
// exit after the index decode. Writes relu(bias) with evict-first stores.
// ---------------------------------------------------------------------------
__global__ void __launch_bounds__(256)
inv_writer_kernel(const int* __restrict__ idx_words,
                  const float* __restrict__ bias,
                  float* __restrict__ out)
{
    // block-local dtype detect (idx header is L2-resident)
    const int tid = threadIdx.x;
    int probe = (tid < 64) ? idx_words[2 * tid + 1] : 0;
    const int is32 = __syncthreads_or(probe != 0);

    const int span = blockIdx.x;
    int w0, w1;
    if (is32) {
        w0 = idx_words[2 * span];
        w1 = idx_words[2 * span + 1];
    } else {
        w0 = idx_words[4 * span];
        w1 = idx_words[4 * span + 2];
    }
    const int s0 = min(max(w0, 0), LL - 1);
    const int e0 = min(max(w1, 0), LL - 1);
    if (s0 <= e0) return;   // valid spans handled by the epilogue

    const int d = tid * 4;
    float4 bb = *(const float4*)(bias + d);
    float4 o;
    o.x = fmaxf(bb.x, 0.0f);
    o.y = fmaxf(bb.y, 0.0f);
    o.z = fmaxf(bb.z, 0.0f);
    o.w = fmaxf(bb.w, 0.0f);
    __stcs((float4*)(out + (size_t)span * DD + d), o);
}

// ---------------------------------------------------------------------------
// Kernel 2a: per-tile partial sums (65536 threads) + dtype detection.
// ---------------------------------------------------------------------------
__global__ void __launch_bounds__(256)
prefix_partial_kernel(const float* __restrict__ P,
                      float* __restrict__ part,
                      const int* __restrict__ idx_words)
{
    if (blockIdx.x == 0 && threadIdx.x == 0) {
        int any = 0;
        #pragma unroll
        for (int j = 0; j < 64; j++) any |= idx_words[2 * j + 1];
        g_is32 = (any != 0) ? 1 : 0;
    }

    const int gidx = blockIdx.x * blockDim.x + threadIdx.x;
    const int e    = gidx & (DD - 1);
    const int tile = (gidx >> 10) & (NT - 1);
    const int b    = gidx >> 13;

    const float* p = P + ((size_t)b * LL + tile * TW) * DD + e;
    float s = 0.0f;
    #pragma unroll
    for (int j = 0; j < TW; j++) s += p[(size_t)j * DD];
    part[((size_t)b * NT + tile) * DD + e] = s;
}

// ---------------------------------------------------------------------------
// Kernel 2b: scan within tile using tile offsets.
// ---------------------------------------------------------------------------
__global__ void __launch_bounds__(256)
prefix_scan_kernel(const float* __restrict__ P,
                   const float* __restrict__ part,
                   float* __restrict__ G)
{
    const int gidx = blockIdx.x * blockDim.x + threadIdx.x;
    const int e    = gidx & (DD - 1);
    const int tile = (gidx >> 10) & (NT - 1);
    const int b    = gidx >> 13;

    float c = 0.0f;
    for (int t = 0; t < tile; t++)
        c += part[((size_t)b * NT + t) * DD + e];

    const float* p = P + ((size_t)b * LL + tile * TW) * DD + e;
    float*       g = G + ((size_t)b * LP1 + tile * TW) * DD + e;

    if (tile == 0) g[0] = 0.0f;

    #pragma unroll 8
    for (int j = 0; j < TW; j++) {
        c += p[(size_t)j * DD];
        g[(size_t)(j + 1) * DD] = c;
    }
}

// ---------------------------------------------------------------------------
// Kernel 3: epilogue, VALID spans only (~41.7us measured).
// ---------------------------------------------------------------------------
__global__ void __launch_bounds__(256)
epilogue_kernel(const int* __restrict__ idx_words,
                const float* __restrict__ G,
                const float* __restrict__ bias,
                float* __restrict__ out)
{
    const int span = blockIdx.x;          // 0 .. B*S-1

    int w0, w1;
    if (g_is32) {
        w0 = idx_words[2 * span];
        w1 = idx_words[2 * span + 1];
    } else {
        w0 = idx_words[4 * span];
        w1 = idx_words[4 * span + 2];
    }
    const int s0 = min(max(w0, 0), LL - 1);
    const int e0 = min(max(w1, 0), LL - 1);
    if (s0 > e0) return;   // written by inv_writer

    const int d = threadIdx.x * 4;
    const int b = span / SS;
    const float inv = 1.0f / (float)(e0 - s0 + 1);
    const float* gs = G + ((size_t)b * LP1 + s0)     * DD;
    const float* ge = G + ((size_t)b * LP1 + e0 + 1) * DD;

    float4 a  = *(const float4*)(ge + d);
    float4 c  = *(const float4*)(gs + d);
    float4 bb = *(const float4*)(bias + d);

    float4 o;
    o.x = fmaxf(fmaf(a.x - c.x, inv, bb.x), 0.0f);
    o.y = fmaxf(fmaf(a.y - c.y, inv, bb.y), 0.0f);
    o.z = fmaxf(fmaf(a.z - c.z, inv, bb.z), 0.0f);
    o.w = fmaxf(fmaf(a.w - c.w, inv, bb.w), 0.0f);

    __stcs((float4*)(out + (size_t)span * DD + d), o);
}

// ---------------------------------------------------------------------------
// launch: fork the invalid-writer onto a non-blocking stream so it overlaps
// the (DRAM-idle) GEMM; join before the epilogue. Event fork/join is the
// capture-legal multi-stream pattern. No device memory is allocated.
// ---------------------------------------------------------------------------
extern "C" void kernel_launch(void* const* d_in, const int* in_sizes, int n_in,
                              void* d_out, int out_size)
{
    const float* h   = nullptr;
    const void*  idx = nullptr;
    const float* W   = nullptr;
    const float* bia = nullptr;
    for (int i = 0; i < n_in; i++) {
        switch (in_sizes[i]) {
            case BB * LL * DD:   h   = (const float*)d_in[i]; break;
            case BB * SS * 2:    idx = d_in[i];               break;
            case DD * DD:        W   = (const float*)d_in[i]; break;
            case DD:             bia = (const float*)d_in[i]; break;
            default: break;
        }
    }

    float *p_s, *g_s, *part_s;
    cudaGetSymbolAddress((void**)&p_s, g_p);
    cudaGetSymbolAddress((void**)&g_s, g_g);
    cudaGetSymbolAddress((void**)&part_s, g_part);

    cudaStream_t s2 = nullptr;
    cudaEvent_t  ev_fork = nullptr, ev_join = nullptr;
    bool forked =
        (cudaStreamCreateWithFlags(&s2, cudaStreamNonBlocking) == cudaSuccess) &&
        (cudaEventCreateWithFlags(&ev_fork, cudaEventDisableTiming) == cudaSuccess) &&
        (cudaEventCreateWithFlags(&ev_join, cudaEventDisableTiming) == cudaSuccess);

    if (forked) {
        cudaEventRecord(ev_fork, 0);              // fork from legacy stream
        cudaStreamWaitEvent(s2, ev_fork, 0);
        inv_writer_kernel<<<NSPAN, 256, 0, s2>>>((const int*)idx, bia,
                                                 (float*)d_out);
        cudaEventRecord(ev_join, s2);
    }

    dim3 gemm_grid(MM / BM, DD / BN);  // 32 x 4
    gemm_f16_kernel<<<gemm_grid, 256>>>(h, W, p_s);

    const int nscan = BB * NT * DD;    // 65536
    prefix_partial_kernel<<<nscan / 256, 256>>>(p_s, part_s, (const int*)idx);
    prefix_scan_kernel<<<nscan / 256, 256>>>(p_s, part_s, g_s);

    if (forked) {
        cudaStreamWaitEvent(0, ev_join, 0);       // join before epilogue
    } else {
        inv_writer_kernel<<<NSPAN, 256>>>((const int*)idx, bia, (float*)d_out);
    }

    epilogue_kernel<<<NSPAN, 256>>>((const int*)idx, g_s, bia, (float*)d_out);
}

// round 13
// speedup vs baseline: 1.1395x; 1.1395x over previous
#include <cuda_runtime.h>
#include <cuda_fp16.h>
#include <cstdint>

// Problem constants
#define BB   8
#define LL   512
#define DD   1024
#define SS   6144
#define NSPAN (BB * SS)    // 49152 spans
#define MM   (BB * LL)     // 4096 GEMM rows
#define LP1  (LL + 1)      // 513 prefix rows
#define NT   16            // prefix tiles along t
#define TW   (LL / NT)     // 32 timesteps per tile
#define SPB  8             // spans per epilogue block

// Scratch (device globals: no allocation allowed)
__device__ float g_p[MM * DD];          // p = h @ W^T          (16 MB)
__device__ float g_g[BB * LP1 * DD];    // prefix sums of p     (16.8 MB)
__device__ float g_part[BB * NT * DD];  // per-tile partial sums (512 KB)
__device__ int   g_is32;                // span_idx dtype flag

// ---------------------------------------------------------------------------
// helpers
// ---------------------------------------------------------------------------
__device__ __forceinline__ void mma_f16(float c[4], const uint32_t a[4], const uint32_t b[2]) {
    asm volatile(
        "mma.sync.aligned.m16n8k16.row.col.f32.f16.f16.f32 "
        "{%0,%1,%2,%3}, {%4,%5,%6,%7}, {%8,%9}, {%0,%1,%2,%3};"
        : "+f"(c[0]), "+f"(c[1]), "+f"(c[2]), "+f"(c[3])
        : "r"(a[0]), "r"(a[1]), "r"(a[2]), "r"(a[3]),
          "r"(b[0]), "r"(b[1]));
}

__device__ __forceinline__ uint32_t pack_half2(float x, float y) {
    __half2 h = __float22half2_rn(make_float2(x, y));
    return *reinterpret_cast<uint32_t*>(&h);
}

// ---------------------------------------------------------------------------
// Kernel 1: GEMM (R10 known-good, ~25us). p[m][n] = sum_d h[m][d] * W[n][d]
// 128x256x32 block tile, 256 threads (8 warps as 2x4), 64x64 warp tiles,
// fp16 m16n8k16 MMA with fp32 accumulate. KPH=40 conflict-free.
// ---------------------------------------------------------------------------
#define BM 128
#define BN 256
#define BK 32
#define KPH 40          // padded row stride in halves

__global__ void __launch_bounds__(256, 1)
gemm_f16_kernel(const float* __restrict__ A,   // h  [4096,1024]
                const float* __restrict__ Wm,  // W  [1024,1024]
                float* __restrict__ P)         // p  [4096,1024]
{
    __shared__ __half As[BM * KPH];   // 10 KB
    __shared__ __half Bs[BN * KPH];   // 20 KB

    const int tid  = threadIdx.x;
    const int warp = tid >> 5;
    const int lane = tid & 31;
    const int wm   = warp >> 2;   // 0..1  (64-row slab)
    const int wn   = warp & 3;    // 0..3  (64-col slab)
    const int m0   = blockIdx.x * BM;
    const int n0   = blockIdx.y * BN;

    const int lr = tid >> 3;
    const int lc = (tid & 7) * 4;

    const float* Ag = A  + (size_t)(m0 + lr) * DD + lc;
    const float* Bg = Wm + (size_t)(n0 + lr) * DD + lc;

    float acc[4][8][4];
    #pragma unroll
    for (int mt = 0; mt < 4; mt++)
        #pragma unroll
        for (int nt = 0; nt < 8; nt++)
            #pragma unroll
            for (int r = 0; r < 4; r++) acc[mt][nt][r] = 0.0f;

    float4 ra[4], rb[8];
    #pragma unroll
    for (int j = 0; j < 4; j++)
        ra[j] = *(const float4*)(Ag + (size_t)j * 32 * DD);
    #pragma unroll
    for (int j = 0; j < 8; j++)
        rb[j] = *(const float4*)(Bg + (size_t)j * 32 * DD);

    const int NKT = DD / BK;  // 32
    for (int kt = 0; kt < NKT; kt++) {
        #pragma unroll
        for (int j = 0; j < 4; j++) {
            float4 a = ra[j];
            uint2 pa;
            pa.x = pack_half2(a.x, a.y); pa.y = pack_half2(a.z, a.w);
            *(uint2*)(&As[(lr + j * 32) * KPH + lc]) = pa;
        }
        #pragma unroll
        for (int j = 0; j < 8; j++) {
            float4 b = rb[j];
            uint2 pb;
            pb.x = pack_half2(b.x, b.y); pb.y = pack_half2(b.z, b.w);
            *(uint2*)(&Bs[(lr + j * 32) * KPH + lc]) = pb;
        }
        __syncthreads();

        if (kt + 1 < NKT) {
            const int ko = (kt + 1) * BK;
            #pragma unroll
            for (int j = 0; j < 4; j++)
                ra[j] = *(const float4*)(Ag + (size_t)j * 32 * DD + ko);
            #pragma unroll
            for (int j = 0; j < 8; j++)
                rb[j] = *(const float4*)(Bg + (size_t)j * 32 * DD + ko);
        }

        #pragma unroll
        for (int ks = 0; ks < 2; ks++) {
            const int kb = ks * 16 + (lane & 3) * 2;
            const int rA = wm * 64 + (lane >> 2);

            uint32_t af[4][4];
            #pragma unroll
            for (int mt = 0; mt < 4; mt++) {
                const int r = rA + mt * 16;
                af[mt][0] = *(const uint32_t*)(&As[r       * KPH + kb]);
                af[mt][1] = *(const uint32_t*)(&As[(r + 8) * KPH + kb]);
                af[mt][2] = *(const uint32_t*)(&As[r       * KPH + kb + 8]);
                af[mt][3] = *(const uint32_t*)(&As[(r + 8) * KPH + kb + 8]);
            }
            uint32_t bf[8][2];
            #pragma unroll
            for (int nt = 0; nt < 8; nt++) {
                const int n = wn * 64 + nt * 8 + (lane >> 2);
                bf[nt][0] = *(const uint32_t*)(&Bs[n * KPH + kb]);
                bf[nt][1] = *(const uint32_t*)(&Bs[n * KPH + kb + 8]);
            }
            #pragma unroll
            for (int mt = 0; mt < 4; mt++)
                #pragma unroll
                for (int nt = 0; nt < 8; nt++)
                    mma_f16(acc[mt][nt], af[mt], bf[nt]);
        }
        __syncthreads();
    }

    const int mrow = m0 + wm * 64 + (lane >> 2);
    const int ncol = n0 + wn * 64 + (lane & 3) * 2;
    #pragma unroll
    for (int mt = 0; mt < 4; mt++) {
        #pragma unroll
        for (int nt = 0; nt < 8; nt++) {
            const int r = mrow + mt * 16;
            const int c = ncol + nt * 8;
            *(float2*)(&P[(size_t)r       * DD + c]) = make_float2(acc[mt][nt][0], acc[mt][nt][1]);
            *(float2*)(&P[(size_t)(r + 8) * DD + c]) = make_float2(acc[mt][nt][2], acc[mt][nt][3]);
        }
    }
}

// ---------------------------------------------------------------------------
// Kernel 2a: per-tile partial sums (131072 threads, NT=16) + dtype detection.
// ---------------------------------------------------------------------------
__global__ void __launch_bounds__(256)
prefix_partial_kernel(const float* __restrict__ P,
                      float* __restrict__ part,
                      const int* __restrict__ idx_words)
{
    if (blockIdx.x == 0 && threadIdx.x == 0) {
        // int64: odd 32-bit words are the zero high halves of values < 512.
        // int32: odd words are 'end' values -- 64 zeros is impossible.
        int any = 0;
        #pragma unroll
        for (int j = 0; j < 64; j++) any |= idx_words[2 * j + 1];
        g_is32 = (any != 0) ? 1 : 0;
    }

    const int gidx = blockIdx.x * blockDim.x + threadIdx.x;  // 0..131071
    const int e    = gidx & (DD - 1);
    const int tile = (gidx >> 10) & (NT - 1);
    const int b    = gidx >> 14;

    const float* p = P + ((size_t)b * LL + tile * TW) * DD + e;
    float s = 0.0f;
    #pragma unroll
    for (int j = 0; j < TW; j++) s += p[(size_t)j * DD];
    part[((size_t)b * NT + tile) * DD + e] = s;
}

// ---------------------------------------------------------------------------
// Kernel 2b: scan within tile using tile offsets (131072 threads).
// ---------------------------------------------------------------------------
__global__ void __launch_bounds__(256)
prefix_scan_kernel(const float* __restrict__ P,
                   const float* __restrict__ part,
                   float* __restrict__ G)
{
    const int gidx = blockIdx.x * blockDim.x + threadIdx.x;
    const int e    = gidx & (DD - 1);
    const int tile = (gidx >> 10) & (NT - 1);
    const int b    = gidx >> 14;

    float c = 0.0f;
    for (int t = 0; t < tile; t++)
        c += part[((size_t)b * NT + t) * DD + e];

    const float* p = P + ((size_t)b * LL + tile * TW) * DD + e;
    float*       g = G + ((size_t)b * LP1 + tile * TW) * DD + e;

    if (tile == 0) g[0] = 0.0f;

    #pragma unroll 8
    for (int j = 0; j < TW; j++) {
        c += p[(size_t)j * DD];
        g[(size_t)(j + 1) * DD] = c;
    }
}

// ---------------------------------------------------------------------------
// Kernel 3: epilogue, 8 spans per block (grid 6144). Threads 0..7 decode the
// block's spans into smem; all 256 threads then issue up to 16 independent
// G-row loads (MLP 16x vs 2x before) before computing. Invalid spans write
// relu(bias) with no G reads.
// ---------------------------------------------------------------------------
__global__ void __launch_bounds__(256)
epilogue_kernel(const int* __restrict__ idx_words,
                const float* __restrict__ G,
                const float* __restrict__ bias,
                float* __restrict__ out)
{
    __shared__ int   s_gs[SPB];
    __shared__ int   s_ge[SPB];
    __shared__ float s_inv[SPB];

    const int tid   = threadIdx.x;
    const int span0 = blockIdx.x * SPB;

    if (tid < SPB) {
        const int span = span0 + tid;
        int w0, w1;
        if (g_is32) {
            w0 = idx_words[2 * span];
            w1 = idx_words[2 * span + 1];
        } else {
            w0 = idx_words[4 * span];
            w1 = idx_words[4 * span + 2];
        }
        const int s0 = min(max(w0, 0), LL - 1);
        const int e0 = min(max(w1, 0), LL - 1);
        if (s0 <= e0) {
            const int b = span / SS;
            s_gs[tid]  = b * LP1 + s0;
            s_ge[tid]  = b * LP1 + e0 + 1;
            s_inv[tid] = 1.0f / (float)(e0 - s0 + 1);
        } else {
            s_gs[tid] = -1;
        }
    }
    __syncthreads();

    const int d = tid * 4;
    const float4 bb = *(const float4*)(bias + d);
    float4 ob;
    ob.x = fmaxf(bb.x, 0.0f);
    ob.y = fmaxf(bb.y, 0.0f);
    ob.z = fmaxf(bb.z, 0.0f);
    ob.w = fmaxf(bb.w, 0.0f);

    // issue all independent gathers first (deep MLP)
    float4 a[SPB], c[SPB];
    #pragma unroll
    for (int j = 0; j < SPB; j++) {
        if (s_gs[j] >= 0) {
            a[j] = *(const float4*)(G + (size_t)s_ge[j] * DD + d);
            c[j] = *(const float4*)(G + (size_t)s_gs[j] * DD + d);
        }
    }

    #pragma unroll
    for (int j = 0; j < SPB; j++) {
        float4 o;
        if (s_gs[j] >= 0) {
            const float inv = s_inv[j];
            o.x = fmaxf(fmaf(a[j].x - c[j].x, inv, bb.x), 0.0f);
            o.y = fmaxf(fmaf(a[j].y - c[j].y, inv, bb.y), 0.0f);
            o.z = fmaxf(fmaf(a[j].z - c[j].z, inv, bb.z), 0.0f);
            o.w = fmaxf(fmaf(a[j].w - c[j].w, inv, bb.w), 0.0f);
        } else {
            o = ob;
        }
        *(float4*)(out + (size_t)(span0 + j) * DD + d) = o;
    }
}

// ---------------------------------------------------------------------------
// launch
// ---------------------------------------------------------------------------
extern "C" void kernel_launch(void* const* d_in, const int* in_sizes, int n_in,
                              void* d_out, int out_size)
{
    const float* h   = nullptr;
    const void*  idx = nullptr;
    const float* W   = nullptr;
    const float* bia = nullptr;
    for (int i = 0; i < n_in; i++) {
        switch (in_sizes[i]) {
            case BB * LL * DD:   h   = (const float*)d_in[i]; break;
            case BB * SS * 2:    idx = d_in[i];               break;
            case DD * DD:        W   = (const float*)d_in[i]; break;
            case DD:             bia = (const float*)d_in[i]; break;
            default: break;
        }
    }

    float *p_s, *g_s, *part_s;
    cudaGetSymbolAddress((void**)&p_s, g_p);
    cudaGetSymbolAddress((void**)&g_s, g_g);
    cudaGetSymbolAddress((void**)&part_s, g_part);

    dim3 gemm_grid(MM / BM, DD / BN);  // 32 x 4
    gemm_f16_kernel<<<gemm_grid, 256>>>(h, W, p_s);

    const int nscan = BB * NT * DD;    // 131072
    prefix_partial_kernel<<<nscan / 256, 256>>>(p_s, part_s, (const int*)idx);
    prefix_scan_kernel<<<nscan / 256, 256>>>(p_s, part_s, g_s);

    epilogue_kernel<<<NSPAN / SPB, 256>>>((const int*)idx, g_s, bia, (float*)d_out);
}

// round 14
// speedup vs baseline: 1.1901x; 1.0444x over previous
#include <cuda_runtime.h>
#include <cuda_fp16.h>
#include <cstdint>

// Problem constants
#define BB   8
#define LL   512
#define DD   1024
#define SS   6144
#define NSPAN (BB * SS)    // 49152 spans
#define MM   (BB * LL)     // 4096 GEMM rows
#define LP1  (LL + 1)      // 513 prefix rows
#define NT   8             // prefix tiles along t
#define TW   (LL / NT)     // 64 timesteps per tile
#define SPB  8             // spans per epilogue block
#define SPG  4             // spans per gather batch (register pressure cap)

// Scratch (device globals: no allocation allowed)
__device__ float g_p[MM * DD];          // p = h @ W^T          (16 MB)
__device__ float g_g[BB * LP1 * DD];    // prefix sums of p     (16.8 MB)
__device__ float g_part[BB * NT * DD];  // per-tile partial sums (256 KB)
__device__ int   g_is32;                // span_idx dtype flag

// ---------------------------------------------------------------------------
// helpers
// ---------------------------------------------------------------------------
__device__ __forceinline__ void mma_f16(float c[4], const uint32_t a[4], const uint32_t b[2]) {
    asm volatile(
        "mma.sync.aligned.m16n8k16.row.col.f32.f16.f16.f32 "
        "{%0,%1,%2,%3}, {%4,%5,%6,%7}, {%8,%9}, {%0,%1,%2,%3};"
        : "+f"(c[0]), "+f"(c[1]), "+f"(c[2]), "+f"(c[3])
        : "r"(a[0]), "r"(a[1]), "r"(a[2]), "r"(a[3]),
          "r"(b[0]), "r"(b[1]));
}

__device__ __forceinline__ uint32_t pack_half2(float x, float y) {
    __half2 h = __float22half2_rn(make_float2(x, y));
    return *reinterpret_cast<uint32_t*>(&h);
}

// ---------------------------------------------------------------------------
// Kernel 1: GEMM (R10 known-good, ~25us). p[m][n] = sum_d h[m][d] * W[n][d]
// 128x256x32 block tile, 256 threads (8 warps as 2x4), 64x64 warp tiles,
// fp16 m16n8k16 MMA with fp32 accumulate. KPH=40 conflict-free.
// ---------------------------------------------------------------------------
#define BM 128
#define BN 256
#define BK 32
#define KPH 40          // padded row stride in halves

__global__ void __launch_bounds__(256, 1)
gemm_f16_kernel(const float* __restrict__ A,   // h  [4096,1024]
                const float* __restrict__ Wm,  // W  [1024,1024]
                float* __restrict__ P)         // p  [4096,1024]
{
    __shared__ __half As[BM * KPH];   // 10 KB
    __shared__ __half Bs[BN * KPH];   // 20 KB

    const int tid  = threadIdx.x;
    const int warp = tid >> 5;
    const int lane = tid & 31;
    const int wm   = warp >> 2;   // 0..1  (64-row slab)
    const int wn   = warp & 3;    // 0..3  (64-col slab)
    const int m0   = blockIdx.x * BM;
    const int n0   = blockIdx.y * BN;

    const int lr = tid >> 3;
    const int lc = (tid & 7) * 4;

    const float* Ag = A  + (size_t)(m0 + lr) * DD + lc;
    const float* Bg = Wm + (size_t)(n0 + lr) * DD + lc;

    float acc[4][8][4];
    #pragma unroll
    for (int mt = 0; mt < 4; mt++)
        #pragma unroll
        for (int nt = 0; nt < 8; nt++)
            #pragma unroll
            for (int r = 0; r < 4; r++) acc[mt][nt][r] = 0.0f;

    float4 ra[4], rb[8];
    #pragma unroll
    for (int j = 0; j < 4; j++)
        ra[j] = *(const float4*)(Ag + (size_t)j * 32 * DD);
    #pragma unroll
    for (int j = 0; j < 8; j++)
        rb[j] = *(const float4*)(Bg + (size_t)j * 32 * DD);

    const int NKT = DD / BK;  // 32
    for (int kt = 0; kt < NKT; kt++) {
        #pragma unroll
        for (int j = 0; j < 4; j++) {
            float4 a = ra[j];
            uint2 pa;
            pa.x = pack_half2(a.x, a.y); pa.y = pack_half2(a.z, a.w);
            *(uint2*)(&As[(lr + j * 32) * KPH + lc]) = pa;
        }
        #pragma unroll
        for (int j = 0; j < 8; j++) {
            float4 b = rb[j];
            uint2 pb;
            pb.x = pack_half2(b.x, b.y); pb.y = pack_half2(b.z, b.w);
            *(uint2*)(&Bs[(lr + j * 32) * KPH + lc]) = pb;
        }
        __syncthreads();

        if (kt + 1 < NKT) {
            const int ko = (kt + 1) * BK;
            #pragma unroll
            for (int j = 0; j < 4; j++)
                ra[j] = *(const float4*)(Ag + (size_t)j * 32 * DD + ko);
            #pragma unroll
            for (int j = 0; j < 8; j++)
                rb[j] = *(const float4*)(Bg + (size_t)j * 32 * DD + ko);
        }

        #pragma unroll
        for (int ks = 0; ks < 2; ks++) {
            const int kb = ks * 16 + (lane & 3) * 2;
            const int rA = wm * 64 + (lane >> 2);

            uint32_t af[4][4];
            #pragma unroll
            for (int mt = 0; mt < 4; mt++) {
                const int r = rA + mt * 16;
                af[mt][0] = *(const uint32_t*)(&As[r       * KPH + kb]);
                af[mt][1] = *(const uint32_t*)(&As[(r + 8) * KPH + kb]);
                af[mt][2] = *(const uint32_t*)(&As[r       * KPH + kb + 8]);
                af[mt][3] = *(const uint32_t*)(&As[(r + 8) * KPH + kb + 8]);
            }
            uint32_t bf[8][2];
            #pragma unroll
            for (int nt = 0; nt < 8; nt++) {
                const int n = wn * 64 + nt * 8 + (lane >> 2);
                bf[nt][0] = *(const uint32_t*)(&Bs[n * KPH + kb]);
                bf[nt][1] = *(const uint32_t*)(&Bs[n * KPH + kb + 8]);
            }
            #pragma unroll
            for (int mt = 0; mt < 4; mt++)
                #pragma unroll
                for (int nt = 0; nt < 8; nt++)
                    mma_f16(acc[mt][nt], af[mt], bf[nt]);
        }
        __syncthreads();
    }

    const int mrow = m0 + wm * 64 + (lane >> 2);
    const int ncol = n0 + wn * 64 + (lane & 3) * 2;
    #pragma unroll
    for (int mt = 0; mt < 4; mt++) {
        #pragma unroll
        for (int nt = 0; nt < 8; nt++) {
            const int r = mrow + mt * 16;
            const int c = ncol + nt * 8;
            *(float2*)(&P[(size_t)r       * DD + c]) = make_float2(acc[mt][nt][0], acc[mt][nt][1]);
            *(float2*)(&P[(size_t)(r + 8) * DD + c]) = make_float2(acc[mt][nt][2], acc[mt][nt][3]);
        }
    }
}

// ---------------------------------------------------------------------------
// Kernel 2a: per-tile partial sums (65536 threads, NT=8) + dtype detection.
// ---------------------------------------------------------------------------
__global__ void __launch_bounds__(256)
prefix_partial_kernel(const float* __restrict__ P,
                      float* __restrict__ part,
                      const int* __restrict__ idx_words)
{
    if (blockIdx.x == 0 && threadIdx.x == 0) {
        // int64: odd 32-bit words are the zero high halves of values < 512.
        // int32: odd words are 'end' values -- 64 zeros is impossible.
        int any = 0;
        #pragma unroll
        for (int j = 0; j < 64; j++) any |= idx_words[2 * j + 1];
        g_is32 = (any != 0) ? 1 : 0;
    }

    const int gidx = blockIdx.x * blockDim.x + threadIdx.x;  // 0..65535
    const int e    = gidx & (DD - 1);
    const int tile = (gidx >> 10) & (NT - 1);
    const int b    = gidx >> 13;

    const float* p = P + ((size_t)b * LL + tile * TW) * DD + e;
    float s = 0.0f;
    #pragma unroll
    for (int j = 0; j < TW; j++) s += p[(size_t)j * DD];
    part[((size_t)b * NT + tile) * DD + e] = s;
}

// ---------------------------------------------------------------------------
// Kernel 2b: scan within tile using tile offsets (65536 threads, NT=8).
// ---------------------------------------------------------------------------
__global__ void __launch_bounds__(256)
prefix_scan_kernel(const float* __restrict__ P,
                   const float* __restrict__ part,
                   float* __restrict__ G)
{
    const int gidx = blockIdx.x * blockDim.x + threadIdx.x;
    const int e    = gidx & (DD - 1);
    const int tile = (gidx >> 10) & (NT - 1);
    const int b    = gidx >> 13;

    float c = 0.0f;
    for (int t = 0; t < tile; t++)
        c += part[((size_t)b * NT + t) * DD + e];

    const float* p = P + ((size_t)b * LL + tile * TW) * DD + e;
    float*       g = G + ((size_t)b * LP1 + tile * TW) * DD + e;

    if (tile == 0) g[0] = 0.0f;

    #pragma unroll 8
    for (int j = 0; j < TW; j++) {
        c += p[(size_t)j * DD];
        g[(size_t)(j + 1) * DD] = c;
    }
}

// ---------------------------------------------------------------------------
// Kernel 3: epilogue, 8 spans per block (grid 6144), gathered in two batches
// of 4 to cap live registers (a[4],c[4] instead of a[8],c[8]) while keeping
// 8 independent G-row loads in flight per batch. Invalid spans write
// relu(bias) with no G reads.
// ---------------------------------------------------------------------------
__global__ void __launch_bounds__(256)
epilogue_kernel(const int* __restrict__ idx_words,
                const float* __restrict__ G,
                const float* __restrict__ bias,
                float* __restrict__ out)
{
    __shared__ int   s_gs[SPB];
    __shared__ int   s_ge[SPB];
    __shared__ float s_inv[SPB];

    const int tid   = threadIdx.x;
    const int span0 = blockIdx.x * SPB;

    if (tid < SPB) {
        const int span = span0 + tid;
        int w0, w1;
        if (g_is32) {
            w0 = idx_words[2 * span];
            w1 = idx_words[2 * span + 1];
        } else {
            w0 = idx_words[4 * span];
            w1 = idx_words[4 * span + 2];
        }
        const int s0 = min(max(w0, 0), LL - 1);
        const int e0 = min(max(w1, 0), LL - 1);
        if (s0 <= e0) {
            const int b = span / SS;
            s_gs[tid]  = b * LP1 + s0;
            s_ge[tid]  = b * LP1 + e0 + 1;
            s_inv[tid] = 1.0f / (float)(e0 - s0 + 1);
        } else {
            s_gs[tid] = -1;
        }
    }
    __syncthreads();

    const int d = tid * 4;
    const float4 bb = *(const float4*)(bias + d);
    float4 ob;
    ob.x = fmaxf(bb.x, 0.0f);
    ob.y = fmaxf(bb.y, 0.0f);
    ob.z = fmaxf(bb.z, 0.0f);
    ob.w = fmaxf(bb.w, 0.0f);

    #pragma unroll
    for (int jb = 0; jb < SPB; jb += SPG) {
        // issue this batch's independent gathers first (MLP 8x)
        float4 a[SPG], c[SPG];
        #pragma unroll
        for (int j = 0; j < SPG; j++) {
            if (s_gs[jb + j] >= 0) {
                a[j] = *(const float4*)(G + (size_t)s_ge[jb + j] * DD + d);
                c[j] = *(const float4*)(G + (size_t)s_gs[jb + j] * DD + d);
            }
        }
        #pragma unroll
        for (int j = 0; j < SPG; j++) {
            float4 o;
            if (s_gs[jb + j] >= 0) {
                const float inv = s_inv[jb + j];
                o.x = fmaxf(fmaf(a[j].x - c[j].x, inv, bb.x), 0.0f);
                o.y = fmaxf(fmaf(a[j].y - c[j].y, inv, bb.y), 0.0f);
                o.z = fmaxf(fmaf(a[j].z - c[j].z, inv, bb.z), 0.0f);
                o.w = fmaxf(fmaf(a[j].w - c[j].w, inv, bb.w), 0.0f);
            } else {
                o = ob;
            }
            *(float4*)(out + (size_t)(span0 + jb + j) * DD + d) = o;
        }
    }
}

// ---------------------------------------------------------------------------
// launch
// ---------------------------------------------------------------------------
extern "C" void kernel_launch(void* const* d_in, const int* in_sizes, int n_in,
                              void* d_out, int out_size)
{
    const float* h   = nullptr;
    const void*  idx = nullptr;
    const float* W   = nullptr;
    const float* bia = nullptr;
    for (int i = 0; i < n_in; i++) {
        switch (in_sizes[i]) {
            case BB * LL * DD:   h   = (const float*)d_in[i]; break;
            case BB * SS * 2:    idx = d_in[i];               break;
            case DD * DD:        W   = (const float*)d_in[i]; break;
            case DD:             bia = (const float*)d_in[i]; break;
            default: break;
        }
    }

    float *p_s, *g_s, *part_s;
    cudaGetSymbolAddress((void**)&p_s, g_p);
    cudaGetSymbolAddress((void**)&g_s, g_g);
    cudaGetSymbolAddress((void**)&part_s, g_part);

    dim3 gemm_grid(MM / BM, DD / BN);  // 32 x 4
    gemm_f16_kernel<<<gemm_grid, 256>>>(h, W, p_s);

    const int nscan = BB * NT * DD;    // 65536
    prefix_partial_kernel<<<nscan / 256, 256>>>(p_s, part_s, (const int*)idx);
    prefix_scan_kernel<<<nscan / 256, 256>>>(p_s, part_s, g_s);

    epilogue_kernel<<<NSPAN / SPB, 256>>>((const int*)idx, g_s, bia, (float*)d_out);
}

// round 15
// speedup vs baseline: 1.2486x; 1.0492x over previous
#include <cuda_runtime.h>
#include <cuda_fp16.h>
#include <cstdint>

// Problem constants
#define BB   8
#define LL   512
#define DD   1024
#define SS   6144
#define NSPAN (BB * SS)    // 49152 spans
#define MM   (BB * LL)     // 4096 GEMM rows
#define LP1  (LL + 1)      // 513 prefix rows
#define NT   32            // prefix tiles along t
#define TW   (LL / NT)     // 16 timesteps per tile
#define SPB  8             // spans per epilogue block
#define SPG  2             // spans per gather batch (register pressure cap)

// Scratch (device globals: no allocation allowed)
__device__ float g_p[MM * DD];          // p = h @ W^T          (16 MB)
__device__ float g_g[BB * LP1 * DD];    // prefix sums of p     (16.8 MB)
__device__ float g_part[BB * NT * DD];  // per-tile partial sums (1 MB)
__device__ int   g_is32;                // span_idx dtype flag

// ---------------------------------------------------------------------------
// helpers
// ---------------------------------------------------------------------------
__device__ __forceinline__ void mma_f16(float c[4], const uint32_t a[4], const uint32_t b[2]) {
    asm volatile(
        "mma.sync.aligned.m16n8k16.row.col.f32.f16.f16.f32 "
        "{%0,%1,%2,%3}, {%4,%5,%6,%7}, {%8,%9}, {%0,%1,%2,%3};"
        : "+f"(c[0]), "+f"(c[1]), "+f"(c[2]), "+f"(c[3])
        : "r"(a[0]), "r"(a[1]), "r"(a[2]), "r"(a[3]),
          "r"(b[0]), "r"(b[1]));
}

__device__ __forceinline__ uint32_t pack_half2(float x, float y) {
    __half2 h = __float22half2_rn(make_float2(x, y));
    return *reinterpret_cast<uint32_t*>(&h);
}

// ---------------------------------------------------------------------------
// Kernel 1: GEMM (known-good, ~35us = fp16 mma.sync ceiling).
// 128x256x32 block tile, 256 threads (8 warps as 2x4), 64x64 warp tiles,
// fp16 m16n8k16 MMA with fp32 accumulate. KPH=40 conflict-free.
// ---------------------------------------------------------------------------
#define BM 128
#define BN 256
#define BK 32
#define KPH 40          // padded row stride in halves

__global__ void __launch_bounds__(256, 1)
gemm_f16_kernel(const float* __restrict__ A,   // h  [4096,1024]
                const float* __restrict__ Wm,  // W  [1024,1024]
                float* __restrict__ P)         // p  [4096,1024]
{
    __shared__ __half As[BM * KPH];   // 10 KB
    __shared__ __half Bs[BN * KPH];   // 20 KB

    const int tid  = threadIdx.x;
    const int warp = tid >> 5;
    const int lane = tid & 31;
    const int wm   = warp >> 2;   // 0..1  (64-row slab)
    const int wn   = warp & 3;    // 0..3  (64-col slab)
    const int m0   = blockIdx.x * BM;
    const int n0   = blockIdx.y * BN;

    const int lr = tid >> 3;
    const int lc = (tid & 7) * 4;

    const float* Ag = A  + (size_t)(m0 + lr) * DD + lc;
    const float* Bg = Wm + (size_t)(n0 + lr) * DD + lc;

    float acc[4][8][4];
    #pragma unroll
    for (int mt = 0; mt < 4; mt++)
        #pragma unroll
        for (int nt = 0; nt < 8; nt++)
            #pragma unroll
            for (int r = 0; r < 4; r++) acc[mt][nt][r] = 0.0f;

    float4 ra[4], rb[8];
    #pragma unroll
    for (int j = 0; j < 4; j++)
        ra[j] = *(const float4*)(Ag + (size_t)j * 32 * DD);
    #pragma unroll
    for (int j = 0; j < 8; j++)
        rb[j] = *(const float4*)(Bg + (size_t)j * 32 * DD);

    const int NKT = DD / BK;  // 32
    for (int kt = 0; kt < NKT; kt++) {
        #pragma unroll
        for (int j = 0; j < 4; j++) {
            float4 a = ra[j];
            uint2 pa;
            pa.x = pack_half2(a.x, a.y); pa.y = pack_half2(a.z, a.w);
            *(uint2*)(&As[(lr + j * 32) * KPH + lc]) = pa;
        }
        #pragma unroll
        for (int j = 0; j < 8; j++) {
            float4 b = rb[j];
            uint2 pb;
            pb.x = pack_half2(b.x, b.y); pb.y = pack_half2(b.z, b.w);
            *(uint2*)(&Bs[(lr + j * 32) * KPH + lc]) = pb;
        }
        __syncthreads();

        if (kt + 1 < NKT) {
            const int ko = (kt + 1) * BK;
            #pragma unroll
            for (int j = 0; j < 4; j++)
                ra[j] = *(const float4*)(Ag + (size_t)j * 32 * DD + ko);
            #pragma unroll
            for (int j = 0; j < 8; j++)
                rb[j] = *(const float4*)(Bg + (size_t)j * 32 * DD + ko);
        }

        #pragma unroll
        for (int ks = 0; ks < 2; ks++) {
            const int kb = ks * 16 + (lane & 3) * 2;
            const int rA = wm * 64 + (lane >> 2);

            uint32_t af[4][4];
            #pragma unroll
            for (int mt = 0; mt < 4; mt++) {
                const int r = rA + mt * 16;
                af[mt][0] = *(const uint32_t*)(&As[r       * KPH + kb]);
                af[mt][1] = *(const uint32_t*)(&As[(r + 8) * KPH + kb]);
                af[mt][2] = *(const uint32_t*)(&As[r       * KPH + kb + 8]);
                af[mt][3] = *(const uint32_t*)(&As[(r + 8) * KPH + kb + 8]);
            }
            uint32_t bf[8][2];
            #pragma unroll
            for (int nt = 0; nt < 8; nt++) {
                const int n = wn * 64 + nt * 8 + (lane >> 2);
                bf[nt][0] = *(const uint32_t*)(&Bs[n * KPH + kb]);
                bf[nt][1] = *(const uint32_t*)(&Bs[n * KPH + kb + 8]);
            }
            #pragma unroll
            for (int mt = 0; mt < 4; mt++)
                #pragma unroll
                for (int nt = 0; nt < 8; nt++)
                    mma_f16(acc[mt][nt], af[mt], bf[nt]);
        }
        __syncthreads();
    }

    const int mrow = m0 + wm * 64 + (lane >> 2);
    const int ncol = n0 + wn * 64 + (lane & 3) * 2;
    #pragma unroll
    for (int mt = 0; mt < 4; mt++) {
        #pragma unroll
        for (int nt = 0; nt < 8; nt++) {
            const int r = mrow + mt * 16;
            const int c = ncol + nt * 8;
            *(float2*)(&P[(size_t)r       * DD + c]) = make_float2(acc[mt][nt][0], acc[mt][nt][1]);
            *(float2*)(&P[(size_t)(r + 8) * DD + c]) = make_float2(acc[mt][nt][2], acc[mt][nt][3]);
        }
    }
}

// ---------------------------------------------------------------------------
// Kernel 2a: per-tile partial sums. NT=32 -> 262144 threads (~1770/SM),
// 16 independent strided loads per thread. + dtype detection.
// ---------------------------------------------------------------------------
__global__ void __launch_bounds__(256)
prefix_partial_kernel(const float* __restrict__ P,
                      float* __restrict__ part,
                      const int* __restrict__ idx_words)
{
    if (blockIdx.x == 0 && threadIdx.x == 0) {
        // int64: odd 32-bit words are the zero high halves of values < 512.
        // int32: odd words are 'end' values -- 64 zeros is impossible.
        int any = 0;
        #pragma unroll
        for (int j = 0; j < 64; j++) any |= idx_words[2 * j + 1];
        g_is32 = (any != 0) ? 1 : 0;
    }

    const int gidx = blockIdx.x * blockDim.x + threadIdx.x;  // 0..262143
    const int e    = gidx & (DD - 1);
    const int tile = (gidx >> 10) & (NT - 1);
    const int b    = gidx >> 15;

    const float* p = P + ((size_t)b * LL + tile * TW) * DD + e;
    float s = 0.0f;
    #pragma unroll
    for (int j = 0; j < TW; j++) s += p[(size_t)j * DD];
    part[((size_t)b * NT + tile) * DD + e] = s;
}

// ---------------------------------------------------------------------------
// Kernel 2b: scan within tile. Offsets from up to 31 INDEPENDENT loads of the
// L2-resident 1MB part array (batched by the compiler), then 16 scan steps.
// 262144 threads.
// ---------------------------------------------------------------------------
__global__ void __launch_bounds__(256)
prefix_scan_kernel(const float* __restrict__ P,
                   const float* __restrict__ part,
                   float* __restrict__ G)
{
    const int gidx = blockIdx.x * blockDim.x + threadIdx.x;
    const int e    = gidx & (DD - 1);
    const int tile = (gidx >> 10) & (NT - 1);
    const int b    = gidx >> 15;

    const float* pb = part + (size_t)b * NT * DD + e;
    float c = 0.0f;
    #pragma unroll 8
    for (int t = 0; t < tile; t++)
        c += pb[(size_t)t * DD];

    const float* p = P + ((size_t)b * LL + tile * TW) * DD + e;
    float*       g = G + ((size_t)b * LP1 + tile * TW) * DD + e;

    if (tile == 0) g[0] = 0.0f;

    #pragma unroll
    for (int j = 0; j < TW; j++) {
        c += p[(size_t)j * DD];
        g[(size_t)(j + 1) * DD] = c;
    }
}

// ---------------------------------------------------------------------------
// Kernel 3: epilogue, 8 spans per block (grid 6144), gathered in batches of
// 2 spans (a[2],c[2] live -> ~44 regs -> occ ~60%+). Invalid spans write
// relu(bias) with no G reads.
// ---------------------------------------------------------------------------
__global__ void __launch_bounds__(256)
epilogue_kernel(const int* __restrict__ idx_words,
                const float* __restrict__ G,
                const float* __restrict__ bias,
                float* __restrict__ out)
{
    __shared__ int   s_gs[SPB];
    __shared__ int   s_ge[SPB];
    __shared__ float s_inv[SPB];

    const int tid   = threadIdx.x;
    const int span0 = blockIdx.x * SPB;

    if (tid < SPB) {
        const int span = span0 + tid;
        int w0, w1;
        if (g_is32) {
            w0 = idx_words[2 * span];
            w1 = idx_words[2 * span + 1];
        } else {
            w0 = idx_words[4 * span];
            w1 = idx_words[4 * span + 2];
        }
        const int s0 = min(max(w0, 0), LL - 1);
        const int e0 = min(max(w1, 0), LL - 1);
        if (s0 <= e0) {
            const int b = span / SS;
            s_gs[tid]  = b * LP1 + s0;
            s_ge[tid]  = b * LP1 + e0 + 1;
            s_inv[tid] = 1.0f / (float)(e0 - s0 + 1);
        } else {
            s_gs[tid] = -1;
        }
    }
    __syncthreads();

    const int d = tid * 4;
    const float4 bb = *(const float4*)(bias + d);
    float4 ob;
    ob.x = fmaxf(bb.x, 0.0f);
    ob.y = fmaxf(bb.y, 0.0f);
    ob.z = fmaxf(bb.z, 0.0f);
    ob.w = fmaxf(bb.w, 0.0f);

    #pragma unroll
    for (int jb = 0; jb < SPB; jb += SPG) {
        float4 a[SPG], c[SPG];
        #pragma unroll
        for (int j = 0; j < SPG; j++) {
            if (s_gs[jb + j] >= 0) {
                a[j] = *(const float4*)(G + (size_t)s_ge[jb + j] * DD + d);
                c[j] = *(const float4*)(G + (size_t)s_gs[jb + j] * DD + d);
            }
        }
        #pragma unroll
        for (int j = 0; j < SPG; j++) {
            float4 o;
            if (s_gs[jb + j] >= 0) {
                const float inv = s_inv[jb + j];
                o.x = fmaxf(fmaf(a[j].x - c[j].x, inv, bb.x), 0.0f);
                o.y = fmaxf(fmaf(a[j].y - c[j].y, inv, bb.y), 0.0f);
                o.z = fmaxf(fmaf(a[j].z - c[j].z, inv, bb.z), 0.0f);
                o.w = fmaxf(fmaf(a[j].w - c[j].w, inv, bb.w), 0.0f);
            } else {
                o = ob;
            }
            *(float4*)(out + (size_t)(span0 + jb + j) * DD + d) = o;
        }
    }
}

// ---------------------------------------------------------------------------
// launch
// ---------------------------------------------------------------------------
extern "C" void kernel_launch(void* const* d_in, const int* in_sizes, int n_in,
                              void* d_out, int out_size)
{
    const float* h   = nullptr;
    const void*  idx = nullptr;
    const float* W   = nullptr;
    const float* bia = nullptr;
    for (int i = 0; i < n_in; i++) {
        switch (in_sizes[i]) {
            case BB * LL * DD:   h   = (const float*)d_in[i]; break;
            case BB * SS * 2:    idx = d_in[i];               break;
            case DD * DD:        W   = (const float*)d_in[i]; break;
            case DD:             bia = (const float*)d_in[i]; break;
            default: break;
        }
    }

    float *p_s, *g_s, *part_s;
    cudaGetSymbolAddress((void**)&p_s, g_p);
    cudaGetSymbolAddress((void**)&g_s, g_g);
    cudaGetSymbolAddress((void**)&part_s, g_part);

    dim3 gemm_grid(MM / BM, DD / BN);  // 32 x 4
    gemm_f16_kernel<<<gemm_grid, 256>>>(h, W, p_s);

    const int nscan = BB * NT * DD;    // 262144
    prefix_partial_kernel<<<nscan / 256, 256>>>(p_s, part_s, (const int*)idx);
    prefix_scan_kernel<<<nscan / 256, 256>>>(p_s, part_s, g_s);

    epilogue_kernel<<<NSPAN / SPB, 256>>>((const int*)idx, g_s, bia, (float*)d_out);
}